// round 5
// baseline (speedup 1.0000x reference)
#include <cuda_runtime.h>
#include <cuda_fp16.h>
#include <cstdint>

#define NN 100000
#define EE 1600000
#define HH 128

// ---------------- scratch (device globals; allocation-free) ----------------
__device__ float  g_h[(size_t)NN * HH];
__device__ float  g_tmp[(size_t)NN * HH];
__device__ float  g_agg[(size_t)NN * HH];
__device__ __half g_x16[(size_t)NN * 64];
__device__ __half g_act16[(size_t)NN * HH];
__device__ float  g_deginv[NN];
__device__ int    g_deg[NN];
__device__ int    g_cursor[NN];
__device__ int    g_rowptr[NN + 1];
__device__ int    g_csr[EE];
__device__ float  g_zl[NN];
__device__ float  g_zr[NN];

// ---------------- CSR build ----------------
__global__ void k_init() {
    int i = blockIdx.x * blockDim.x + threadIdx.x;
    if (i < NN) { g_deg[i] = 0; g_cursor[i] = 0; }
}

// edge_index is int32 (JAX x64 disabled => jnp.int64 silently becomes int32)
__global__ void k_count(const int* __restrict__ ei) {
    int e = blockIdx.x * blockDim.x + threadIdx.x;
    if (e >= EE) return;
    int d = ei[EE + e];
    d = min(max(d, 0), NN - 1);
    atomicAdd(&g_deg[d], 1);
}

__global__ __launch_bounds__(1024) void k_scan() {
    __shared__ int carry;
    __shared__ int wsum[32];
    int lane = threadIdx.x & 31;
    int w = threadIdx.x >> 5;
    if (threadIdx.x == 0) carry = 0;
    __syncthreads();
    for (int base = 0; base < NN; base += 1024) {
        int i = base + threadIdx.x;
        int v = (i < NN) ? g_deg[i] : 0;
        int x = v;
        #pragma unroll
        for (int d = 1; d < 32; d <<= 1) {
            int y = __shfl_up_sync(0xffffffffu, x, d);
            if (lane >= d) x += y;
        }
        if (lane == 31) wsum[w] = x;
        __syncthreads();
        if (w == 0) {
            int s = wsum[lane];
            #pragma unroll
            for (int d = 1; d < 32; d <<= 1) {
                int y = __shfl_up_sync(0xffffffffu, s, d);
                if (lane >= d) s += y;
            }
            wsum[lane] = s;
        }
        __syncthreads();
        int offset = carry + (w > 0 ? wsum[w - 1] : 0);
        int incl = offset + x;
        if (i < NN) {
            g_rowptr[i] = incl - v;
            g_deginv[i] = 1.0f / fmaxf((float)v, 1.0f);
        }
        __syncthreads();
        if (threadIdx.x == 1023) carry = incl;
        __syncthreads();
    }
    if (threadIdx.x == 0) g_rowptr[NN] = carry;
}

__global__ void k_fill(const int* __restrict__ ei) {
    int e = blockIdx.x * blockDim.x + threadIdx.x;
    if (e >= EE) return;
    int s = ei[e];
    int d = ei[EE + e];
    s = min(max(s, 0), NN - 1);
    d = min(max(d, 0), NN - 1);
    int p = atomicAdd(&g_cursor[d], 1);
    g_csr[g_rowptr[d] + p] = s;
}

// ---------------- x -> fp16 convert ----------------
__global__ void k_conv_x16(const float* __restrict__ x, __half* __restrict__ x16) {
    int i = blockIdx.x * blockDim.x + threadIdx.x;   // half2 index
    if (i >= NN * 32) return;
    float2 v = ((const float2*)x)[i];
    ((__half2*)x16)[i] = __float22half2_rn(v);
}

// ---------------- aggregation: warp per dst node, fp16 gather, 4-way MLP ----------------
// F=128: lane loads 4 halves (8B); F=64: lane loads 2 halves (4B)
template <int F>
__global__ __launch_bounds__(256) void agg_kernel(const __half* __restrict__ in,
                                                  float* __restrict__ out) {
    int warp = (blockIdx.x * blockDim.x + threadIdx.x) >> 5;
    int lane = threadIdx.x & 31;
    if (warp >= NN) return;
    int s = g_rowptr[warp], e = g_rowptr[warp + 1];
    float dinv = g_deginv[warp];
    if (F == 128) {
        float a0 = 0.f, a1 = 0.f, a2 = 0.f, a3 = 0.f;
        int j = s;
        for (; j + 4 <= e; j += 4) {
            int s0 = g_csr[j], s1 = g_csr[j + 1], s2 = g_csr[j + 2], s3 = g_csr[j + 3];
            uint2 v0 = __ldg((const uint2*)(in + (size_t)s0 * 128) + lane);
            uint2 v1 = __ldg((const uint2*)(in + (size_t)s1 * 128) + lane);
            uint2 v2 = __ldg((const uint2*)(in + (size_t)s2 * 128) + lane);
            uint2 v3 = __ldg((const uint2*)(in + (size_t)s3 * 128) + lane);
            float2 f;
            f = __half22float2(*(__half2*)&v0.x); a0 += f.x; a1 += f.y;
            f = __half22float2(*(__half2*)&v0.y); a2 += f.x; a3 += f.y;
            f = __half22float2(*(__half2*)&v1.x); a0 += f.x; a1 += f.y;
            f = __half22float2(*(__half2*)&v1.y); a2 += f.x; a3 += f.y;
            f = __half22float2(*(__half2*)&v2.x); a0 += f.x; a1 += f.y;
            f = __half22float2(*(__half2*)&v2.y); a2 += f.x; a3 += f.y;
            f = __half22float2(*(__half2*)&v3.x); a0 += f.x; a1 += f.y;
            f = __half22float2(*(__half2*)&v3.y); a2 += f.x; a3 += f.y;
        }
        for (; j < e; j++) {
            int src = g_csr[j];
            uint2 v = __ldg((const uint2*)(in + (size_t)src * 128) + lane);
            float2 f;
            f = __half22float2(*(__half2*)&v.x); a0 += f.x; a1 += f.y;
            f = __half22float2(*(__half2*)&v.y); a2 += f.x; a3 += f.y;
        }
        float4 o; o.x = a0 * dinv; o.y = a1 * dinv; o.z = a2 * dinv; o.w = a3 * dinv;
        *(float4*)(out + (size_t)warp * 128 + lane * 4) = o;
    } else {  // F == 64
        float a0 = 0.f, a1 = 0.f;
        int j = s;
        for (; j + 4 <= e; j += 4) {
            int s0 = g_csr[j], s1 = g_csr[j + 1], s2 = g_csr[j + 2], s3 = g_csr[j + 3];
            uint32_t v0 = __ldg((const uint32_t*)(in + (size_t)s0 * 64) + lane);
            uint32_t v1 = __ldg((const uint32_t*)(in + (size_t)s1 * 64) + lane);
            uint32_t v2 = __ldg((const uint32_t*)(in + (size_t)s2 * 64) + lane);
            uint32_t v3 = __ldg((const uint32_t*)(in + (size_t)s3 * 64) + lane);
            float2 f;
            f = __half22float2(*(__half2*)&v0); a0 += f.x; a1 += f.y;
            f = __half22float2(*(__half2*)&v1); a0 += f.x; a1 += f.y;
            f = __half22float2(*(__half2*)&v2); a0 += f.x; a1 += f.y;
            f = __half22float2(*(__half2*)&v3); a0 += f.x; a1 += f.y;
        }
        for (; j < e; j++) {
            int src = g_csr[j];
            uint32_t v = __ldg((const uint32_t*)(in + (size_t)src * 64) + lane);
            float2 f = __half22float2(*(__half2*)&v);
            a0 += f.x; a1 += f.y;
        }
        float2 o; o.x = a0 * dinv; o.y = a1 * dinv;
        *(float2*)(out + (size_t)warp * 64 + lane * 2) = o;
    }
}

// ---------------- tf32 mma.sync GEMM ----------------
// C = A1@W1 (+ A2@W2) + bias, optional relu, optional fp16 shadow copy.
__device__ __forceinline__ uint32_t f2tf32(float x) {
    uint32_t r;
    asm("cvt.rna.tf32.f32 %0, %1;" : "=r"(r) : "f"(x));
    return r;
}

#define SA_STRIDE 36
#define SB_STRIDE 132

__global__ __launch_bounds__(256, 2) void gemm_tc(
    const float* __restrict__ A1, const float* __restrict__ W1,
    const float* __restrict__ A2, const float* __restrict__ W2,
    const float* __restrict__ bias, float* __restrict__ C,
    __half* __restrict__ C16, int K, int dual, int relu)
{
    __shared__ uint32_t sA[128 * SA_STRIDE];
    __shared__ uint32_t sB[32 * SB_STRIDE];

    int tid = threadIdx.x;
    int wid = tid >> 5, lane = tid & 31;
    int g = lane >> 2, t = lane & 3;
    int row0 = blockIdx.x * 128;
    int mrow = (wid & 3) * 32;
    int ncol = (wid >> 2) * 64;

    float acc[2][8][4];
    #pragma unroll
    for (int mi = 0; mi < 2; mi++)
        #pragma unroll
        for (int nj = 0; nj < 8; nj++)
            #pragma unroll
            for (int q = 0; q < 4; q++) acc[mi][nj][q] = 0.f;

    int KT = dual ? 2 * K : K;
    for (int k0 = 0; k0 < KT; k0 += 32) {
        const float* A = A1;
        const float* W = W1;
        int kk = k0;
        if (k0 >= K) { A = A2; W = W2; kk = k0 - K; }

        #pragma unroll
        for (int it = 0; it < 4; it++) {
            int idx = tid + it * 256;
            int r = idx >> 3;
            int c4 = idx & 7;
            float4 v = make_float4(0.f, 0.f, 0.f, 0.f);
            int gr = row0 + r;
            if (gr < NN) v = *(const float4*)&A[(size_t)gr * K + kk + c4 * 4];
            uint32_t* p = &sA[r * SA_STRIDE + c4 * 4];
            p[0] = f2tf32(v.x); p[1] = f2tf32(v.y);
            p[2] = f2tf32(v.z); p[3] = f2tf32(v.w);
        }
        #pragma unroll
        for (int it = 0; it < 4; it++) {
            int idx = tid + it * 256;
            int kr = idx >> 5;
            int n4 = idx & 31;
            float4 v = *(const float4*)&W[(size_t)(kk + kr) * 128 + n4 * 4];
            uint32_t* p = &sB[kr * SB_STRIDE + n4 * 4];
            p[0] = f2tf32(v.x); p[1] = f2tf32(v.y);
            p[2] = f2tf32(v.z); p[3] = f2tf32(v.w);
        }
        __syncthreads();

        #pragma unroll
        for (int ks = 0; ks < 4; ks++) {
            int k = ks * 8;
            uint32_t af[2][4];
            #pragma unroll
            for (int mi = 0; mi < 2; mi++) {
                int br = mrow + mi * 16;
                af[mi][0] = sA[(br + g) * SA_STRIDE + k + t];
                af[mi][1] = sA[(br + g + 8) * SA_STRIDE + k + t];
                af[mi][2] = sA[(br + g) * SA_STRIDE + k + t + 4];
                af[mi][3] = sA[(br + g + 8) * SA_STRIDE + k + t + 4];
            }
            uint32_t bf[8][2];
            #pragma unroll
            for (int nj = 0; nj < 8; nj++) {
                int col = ncol + nj * 8 + g;
                bf[nj][0] = sB[(k + t) * SB_STRIDE + col];
                bf[nj][1] = sB[(k + t + 4) * SB_STRIDE + col];
            }
            #pragma unroll
            for (int mi = 0; mi < 2; mi++)
                #pragma unroll
                for (int nj = 0; nj < 8; nj++) {
                    asm volatile(
                        "mma.sync.aligned.m16n8k8.row.col.f32.tf32.tf32.f32 "
                        "{%0,%1,%2,%3}, {%4,%5,%6,%7}, {%8,%9}, {%0,%1,%2,%3};"
                        : "+f"(acc[mi][nj][0]), "+f"(acc[mi][nj][1]),
                          "+f"(acc[mi][nj][2]), "+f"(acc[mi][nj][3])
                        : "r"(af[mi][0]), "r"(af[mi][1]), "r"(af[mi][2]), "r"(af[mi][3]),
                          "r"(bf[nj][0]), "r"(bf[nj][1]));
                }
        }
        __syncthreads();
    }

    #pragma unroll
    for (int mi = 0; mi < 2; mi++) {
        int r_lo = row0 + mrow + mi * 16 + g;
        int r_hi = r_lo + 8;
        #pragma unroll
        for (int nj = 0; nj < 8; nj++) {
            int col = ncol + nj * 8 + 2 * t;
            float b0 = bias[col], b1 = bias[col + 1];
            float2 v0, v1;
            v0.x = acc[mi][nj][0] + b0; v0.y = acc[mi][nj][1] + b1;
            v1.x = acc[mi][nj][2] + b0; v1.y = acc[mi][nj][3] + b1;
            if (relu) {
                v0.x = fmaxf(v0.x, 0.f); v0.y = fmaxf(v0.y, 0.f);
                v1.x = fmaxf(v1.x, 0.f); v1.y = fmaxf(v1.y, 0.f);
            }
            if (r_lo < NN) {
                *(float2*)&C[(size_t)r_lo * 128 + col] = v0;
                if (C16) *(__half2*)&C16[(size_t)r_lo * 128 + col] = __float22half2_rn(v0);
            }
            if (r_hi < NN) {
                *(float2*)&C[(size_t)r_hi * 128 + col] = v1;
                if (C16) *(__half2*)&C16[(size_t)r_hi * 128 + col] = __float22half2_rn(v1);
            }
        }
    }
}

// ---------------- layernorm + relu + residual-add: h += relu(LN(u)), fp16 shadow ----------------
__global__ __launch_bounds__(256) void ln_res_kernel(const float* __restrict__ u,
                                                     const float* __restrict__ g,
                                                     const float* __restrict__ b,
                                                     float* __restrict__ h,
                                                     __half* __restrict__ h16) {
    int warp = (blockIdx.x * blockDim.x + threadIdx.x) >> 5;
    int lane = threadIdx.x & 31;
    if (warp >= NN) return;
    float4 v = ((const float4*)(u + (size_t)warp * 128))[lane];
    float s = v.x + v.y + v.z + v.w;
    #pragma unroll
    for (int d = 16; d; d >>= 1) s += __shfl_xor_sync(0xffffffffu, s, d);
    float mu = s * (1.0f / 128.0f);
    float dx = v.x - mu, dy = v.y - mu, dz = v.z - mu, dw = v.w - mu;
    float q = dx * dx + dy * dy + dz * dz + dw * dw;
    #pragma unroll
    for (int d = 16; d; d >>= 1) q += __shfl_xor_sync(0xffffffffu, q, d);
    float r = rsqrtf(q * (1.0f / 128.0f) + 1e-5f);
    float4 gg = ((const float4*)g)[lane];
    float4 bb = ((const float4*)b)[lane];
    float4* hp = (float4*)(h + (size_t)warp * 128);
    float4 hv = hp[lane];
    hv.x += fmaxf(dx * r * gg.x + bb.x, 0.f);
    hv.y += fmaxf(dy * r * gg.y + bb.y, 0.f);
    hv.z += fmaxf(dz * r * gg.z + bb.z, 0.f);
    hv.w += fmaxf(dw * r * gg.w + bb.w, 0.f);
    hp[lane] = hv;
    __half2* hq = (__half2*)(h16 + (size_t)warp * 128 + lane * 4);
    hq[0] = __float22half2_rn(make_float2(hv.x, hv.y));
    hq[1] = __float22half2_rn(make_float2(hv.z, hv.w));
}

// ---------------- layer 4: project h to scalars ----------------
__global__ __launch_bounds__(256) void gemv4_kernel(const float* __restrict__ h,
                                                    const float* __restrict__ wl,
                                                    const float* __restrict__ wr) {
    int warp = (blockIdx.x * blockDim.x + threadIdx.x) >> 5;
    int lane = threadIdx.x & 31;
    if (warp >= NN) return;
    float4 v = ((const float4*)(h + (size_t)warp * 128))[lane];
    float4 a = __ldg((const float4*)wl + lane);
    float4 b = __ldg((const float4*)wr + lane);
    float sl = v.x * a.x + v.y * a.y + v.z * a.z + v.w * a.w;
    float sr = v.x * b.x + v.y * b.y + v.z * b.z + v.w * b.w;
    #pragma unroll
    for (int d = 16; d; d >>= 1) {
        sl += __shfl_xor_sync(0xffffffffu, sl, d);
        sr += __shfl_xor_sync(0xffffffffu, sr, d);
    }
    if (lane == 0) { g_zl[warp] = sl; g_zr[warp] = sr; }
}

__global__ void final_kernel(const float* __restrict__ b4, float* __restrict__ out) {
    int i = blockIdx.x * blockDim.x + threadIdx.x;
    if (i >= NN) return;
    int s = g_rowptr[i], e = g_rowptr[i + 1];
    float sum = 0.f;
    int j = s;
    for (; j + 4 <= e; j += 4) {
        float z0 = __ldg(&g_zl[g_csr[j]]);
        float z1 = __ldg(&g_zl[g_csr[j + 1]]);
        float z2 = __ldg(&g_zl[g_csr[j + 2]]);
        float z3 = __ldg(&g_zl[g_csr[j + 3]]);
        sum += (z0 + z1) + (z2 + z3);
    }
    for (; j < e; j++) sum += __ldg(&g_zl[g_csr[j]]);
    out[i] = g_zr[i] + b4[0] + g_deginv[i] * sum;
}

// ---------------- host ----------------
template <typename T>
static T* sym(const void* s) {
    void* p = nullptr;
    cudaGetSymbolAddress(&p, s);
    return (T*)p;
}

extern "C" void kernel_launch(void* const* d_in, const int* in_sizes, int n_in,
                              void* d_out, int out_size) {
    const float* x    = (const float*)d_in[0];
    const int*   ei   = (const int*)d_in[1];     // int32 (JAX x64 disabled)
    const float* Wl1  = (const float*)d_in[2];
    const float* Wr1  = (const float*)d_in[3];
    const float* b1   = (const float*)d_in[4];
    const float* ln_g = (const float*)d_in[5];
    const float* ln_b = (const float*)d_in[6];
    const float* Wres = (const float*)d_in[7];
    const float* bres = (const float*)d_in[8];
    const float* Wl2  = (const float*)d_in[9];
    const float* Wr2  = (const float*)d_in[10];
    const float* b2   = (const float*)d_in[11];
    const float* Wl3  = (const float*)d_in[12];
    const float* Wr3  = (const float*)d_in[13];
    const float* b3   = (const float*)d_in[14];
    const float* Wl4  = (const float*)d_in[15];
    const float* Wr4  = (const float*)d_in[16];
    const float* b4   = (const float*)d_in[17];
    float* out = (float*)d_out;

    float*  hp    = sym<float>(g_h);
    float*  tmpp  = sym<float>(g_tmp);
    float*  aggp  = sym<float>(g_agg);
    __half* x16   = sym<__half>(g_x16);
    __half* act16 = sym<__half>(g_act16);

    const int warpBlocks = (NN + 7) / 8;
    const int gemmBlocks = (NN + 127) / 128;      // 782
    const int edgeBlocks = (EE + 255) / 256;
    const int nodeBlocks = (NN + 255) / 256;
    const int convBlocks = (NN * 32 + 255) / 256;

    // CSR build + x16 convert
    k_init<<<nodeBlocks, 256>>>();
    k_count<<<edgeBlocks, 256>>>(ei);
    k_conv_x16<<<convBlocks, 256>>>(x, x16);
    k_scan<<<1, 1024>>>();
    k_fill<<<edgeBlocks, 256>>>(ei);

    // Layer 1
    agg_kernel<64><<<warpBlocks, 256>>>(x16, aggp);
    // residual: h = x @ Wres + bres
    gemm_tc<<<gemmBlocks, 256>>>(x, Wres, nullptr, nullptr, bres, hp, nullptr, 64, 0, 0);
    // u = agg @ Wl1 + x @ Wr1 + b1
    gemm_tc<<<gemmBlocks, 256>>>(aggp, Wl1, x, Wr1, b1, tmpp, nullptr, 64, 1, 0);
    // h += relu(LN(u)), h16 shadow
    ln_res_kernel<<<warpBlocks, 256>>>(tmpp, ln_g, ln_b, hp, act16);

    // Layer 2: tmp = relu(agg(h) @ Wl2 + h @ Wr2 + b2), tmp16 shadow
    agg_kernel<128><<<warpBlocks, 256>>>(act16, aggp);
    gemm_tc<<<gemmBlocks, 256>>>(aggp, Wl2, hp, Wr2, b2, tmpp, act16, 128, 1, 1);

    // Layer 3: h = relu(agg(tmp) @ Wl3 + tmp @ Wr3 + b3)
    agg_kernel<128><<<warpBlocks, 256>>>(act16, aggp);
    gemm_tc<<<gemmBlocks, 256>>>(aggp, Wl3, tmpp, Wr3, b3, hp, nullptr, 128, 1, 1);

    // Layer 4
    gemv4_kernel<<<warpBlocks, 256>>>(hp, Wl4, Wr4);
    final_kernel<<<nodeBlocks, 256>>>(b4, out);
}

// round 6
// speedup vs baseline: 1.1334x; 1.1334x over previous
#include <cuda_runtime.h>
#include <cstdint>

#define NN 100000
#define EE 1600000
#define HH 128
#define NB ((NN + 1023) / 1024)   // 98 scan tiles

// ---------------- scratch (device globals; allocation-free) ----------------
__device__ float g_h[(size_t)NN * HH];
__device__ float g_tmp[(size_t)NN * HH];
__device__ float g_agg[(size_t)NN * HH];
__device__ float g_deginv[NN];
__device__ int   g_deg[NN];
__device__ int   g_cursor[NN];
__device__ int   g_rowptr[NN + 1];
__device__ int   g_bsum[NB];
__device__ int   g_csr[EE];
__device__ float g_zl[NN];
__device__ float g_zr[NN];

// ---------------- CSR build ----------------
__global__ void k_init() {
    int i = blockIdx.x * blockDim.x + threadIdx.x;
    if (i < NN) { g_deg[i] = 0; g_cursor[i] = 0; }
}

// edge_index is int32 (JAX x64 disabled => jnp.int64 silently becomes int32)
__global__ void k_count(const int* __restrict__ ei) {
    int e = blockIdx.x * blockDim.x + threadIdx.x;
    if (e >= EE) return;
    int d = ei[EE + e];
    d = min(max(d, 0), NN - 1);
    atomicAdd(&g_deg[d], 1);
}

// pass 1: per-tile (1024) exclusive scan; tile totals to g_bsum; deginv
__global__ __launch_bounds__(1024) void k_scan1() {
    __shared__ int wsum[32];
    int t = threadIdx.x;
    int lane = t & 31, w = t >> 5;
    int i = blockIdx.x * 1024 + t;
    int v = (i < NN) ? g_deg[i] : 0;
    int x = v;
    #pragma unroll
    for (int d = 1; d < 32; d <<= 1) {
        int y = __shfl_up_sync(0xffffffffu, x, d);
        if (lane >= d) x += y;
    }
    if (lane == 31) wsum[w] = x;
    __syncthreads();
    if (w == 0) {
        int s = wsum[lane];
        #pragma unroll
        for (int d = 1; d < 32; d <<= 1) {
            int y = __shfl_up_sync(0xffffffffu, s, d);
            if (lane >= d) s += y;
        }
        wsum[lane] = s;
    }
    __syncthreads();
    int incl = x + (w > 0 ? wsum[w - 1] : 0);
    if (i < NN) {
        g_rowptr[i] = incl - v;                       // tile-local exclusive
        g_deginv[i] = 1.0f / fmaxf((float)v, 1.0f);
    }
    if (t == 1023) g_bsum[blockIdx.x] = incl;         // tile total
}

// pass 2: scan the 98 tile totals (single tiny block)
__global__ __launch_bounds__(128) void k_scan2() {
    __shared__ int wsum[4];
    int t = threadIdx.x;
    int lane = t & 31, w = t >> 5;
    int v = (t < NB) ? g_bsum[t] : 0;
    int x = v;
    #pragma unroll
    for (int d = 1; d < 32; d <<= 1) {
        int y = __shfl_up_sync(0xffffffffu, x, d);
        if (lane >= d) x += y;
    }
    if (lane == 31) wsum[w] = x;
    __syncthreads();
    if (t < 4) {
        int s = wsum[t];
        if (t >= 1) s += wsum[0];
        if (t >= 2) s += wsum[1];
        if (t >= 3) s += wsum[2];
        wsum[t] = s;
    }
    __syncthreads();
    int incl = x + (w > 0 ? wsum[w - 1] : 0);
    if (t < NB) g_bsum[t] = incl - v;                 // exclusive tile offsets
    if (t == NB - 1) g_rowptr[NN] = incl;             // grand total (== EE)
}

// pass 3: add tile offsets
__global__ __launch_bounds__(1024) void k_scan3() {
    int i = blockIdx.x * 1024 + threadIdx.x;
    if (i < NN) g_rowptr[i] += g_bsum[blockIdx.x];
}

__global__ void k_fill(const int* __restrict__ ei) {
    int e = blockIdx.x * blockDim.x + threadIdx.x;
    if (e >= EE) return;
    int s = ei[e];
    int d = ei[EE + e];
    s = min(max(s, 0), NN - 1);
    d = min(max(d, 0), NN - 1);
    int p = atomicAdd(&g_cursor[d], 1);
    g_csr[g_rowptr[d] + p] = s;
}

// ---------------- aggregation: warp per dst node, fp32 gather, 4-way MLP ----------------
template <int F>
__global__ __launch_bounds__(256) void agg_kernel(const float* __restrict__ in,
                                                  float* __restrict__ out) {
    int warp = (blockIdx.x * blockDim.x + threadIdx.x) >> 5;
    int lane = threadIdx.x & 31;
    if (warp >= NN) return;
    int s = g_rowptr[warp], e = g_rowptr[warp + 1];
    float dinv = g_deginv[warp];
    if (F == 128) {
        float a0 = 0.f, a1 = 0.f, a2 = 0.f, a3 = 0.f;
        int j = s;
        for (; j + 4 <= e; j += 4) {
            int s0 = g_csr[j], s1 = g_csr[j + 1], s2 = g_csr[j + 2], s3 = g_csr[j + 3];
            float4 v0 = __ldg((const float4*)(in + (size_t)s0 * 128) + lane);
            float4 v1 = __ldg((const float4*)(in + (size_t)s1 * 128) + lane);
            float4 v2 = __ldg((const float4*)(in + (size_t)s2 * 128) + lane);
            float4 v3 = __ldg((const float4*)(in + (size_t)s3 * 128) + lane);
            a0 += v0.x + v1.x + v2.x + v3.x;
            a1 += v0.y + v1.y + v2.y + v3.y;
            a2 += v0.z + v1.z + v2.z + v3.z;
            a3 += v0.w + v1.w + v2.w + v3.w;
        }
        for (; j < e; j++) {
            int src = g_csr[j];
            float4 v = __ldg((const float4*)(in + (size_t)src * 128) + lane);
            a0 += v.x; a1 += v.y; a2 += v.z; a3 += v.w;
        }
        float4 o; o.x = a0 * dinv; o.y = a1 * dinv; o.z = a2 * dinv; o.w = a3 * dinv;
        ((float4*)(out + (size_t)warp * 128))[lane] = o;
    } else {  // F == 64
        float a0 = 0.f, a1 = 0.f;
        int j = s;
        for (; j + 4 <= e; j += 4) {
            int s0 = g_csr[j], s1 = g_csr[j + 1], s2 = g_csr[j + 2], s3 = g_csr[j + 3];
            float2 v0 = __ldg((const float2*)(in + (size_t)s0 * 64) + lane);
            float2 v1 = __ldg((const float2*)(in + (size_t)s1 * 64) + lane);
            float2 v2 = __ldg((const float2*)(in + (size_t)s2 * 64) + lane);
            float2 v3 = __ldg((const float2*)(in + (size_t)s3 * 64) + lane);
            a0 += v0.x + v1.x + v2.x + v3.x;
            a1 += v0.y + v1.y + v2.y + v3.y;
        }
        for (; j < e; j++) {
            int src = g_csr[j];
            float2 v = __ldg((const float2*)(in + (size_t)src * 64) + lane);
            a0 += v.x; a1 += v.y;
        }
        float2 o; o.x = a0 * dinv; o.y = a1 * dinv;
        ((float2*)(out + (size_t)warp * 64))[lane] = o;
    }
}

// ---------------- tf32 mma.sync GEMM ----------------
__device__ __forceinline__ uint32_t f2tf32(float x) {
    uint32_t r;
    asm("cvt.rna.tf32.f32 %0, %1;" : "=r"(r) : "f"(x));
    return r;
}

#define SA_STRIDE 36
#define SB_STRIDE 132

__global__ __launch_bounds__(256, 2) void gemm_tc(
    const float* __restrict__ A1, const float* __restrict__ W1,
    const float* __restrict__ A2, const float* __restrict__ W2,
    const float* __restrict__ bias, float* __restrict__ C,
    int K, int dual, int relu)
{
    __shared__ uint32_t sA[128 * SA_STRIDE];
    __shared__ uint32_t sB[32 * SB_STRIDE];

    int tid = threadIdx.x;
    int wid = tid >> 5, lane = tid & 31;
    int g = lane >> 2, t = lane & 3;
    int row0 = blockIdx.x * 128;
    int mrow = (wid & 3) * 32;
    int ncol = (wid >> 2) * 64;

    float acc[2][8][4];
    #pragma unroll
    for (int mi = 0; mi < 2; mi++)
        #pragma unroll
        for (int nj = 0; nj < 8; nj++)
            #pragma unroll
            for (int q = 0; q < 4; q++) acc[mi][nj][q] = 0.f;

    int KT = dual ? 2 * K : K;
    for (int k0 = 0; k0 < KT; k0 += 32) {
        const float* A = A1;
        const float* W = W1;
        int kk = k0;
        if (k0 >= K) { A = A2; W = W2; kk = k0 - K; }

        #pragma unroll
        for (int it = 0; it < 4; it++) {
            int idx = tid + it * 256;
            int r = idx >> 3;
            int c4 = idx & 7;
            float4 v = make_float4(0.f, 0.f, 0.f, 0.f);
            int gr = row0 + r;
            if (gr < NN) v = *(const float4*)&A[(size_t)gr * K + kk + c4 * 4];
            uint32_t* p = &sA[r * SA_STRIDE + c4 * 4];
            p[0] = f2tf32(v.x); p[1] = f2tf32(v.y);
            p[2] = f2tf32(v.z); p[3] = f2tf32(v.w);
        }
        #pragma unroll
        for (int it = 0; it < 4; it++) {
            int idx = tid + it * 256;
            int kr = idx >> 5;
            int n4 = idx & 31;
            float4 v = *(const float4*)&W[(size_t)(kk + kr) * 128 + n4 * 4];
            uint32_t* p = &sB[kr * SB_STRIDE + n4 * 4];
            p[0] = f2tf32(v.x); p[1] = f2tf32(v.y);
            p[2] = f2tf32(v.z); p[3] = f2tf32(v.w);
        }
        __syncthreads();

        #pragma unroll
        for (int ks = 0; ks < 4; ks++) {
            int k = ks * 8;
            uint32_t af[2][4];
            #pragma unroll
            for (int mi = 0; mi < 2; mi++) {
                int br = mrow + mi * 16;
                af[mi][0] = sA[(br + g) * SA_STRIDE + k + t];
                af[mi][1] = sA[(br + g + 8) * SA_STRIDE + k + t];
                af[mi][2] = sA[(br + g) * SA_STRIDE + k + t + 4];
                af[mi][3] = sA[(br + g + 8) * SA_STRIDE + k + t + 4];
            }
            uint32_t bf[8][2];
            #pragma unroll
            for (int nj = 0; nj < 8; nj++) {
                int col = ncol + nj * 8 + g;
                bf[nj][0] = sB[(k + t) * SB_STRIDE + col];
                bf[nj][1] = sB[(k + t + 4) * SB_STRIDE + col];
            }
            #pragma unroll
            for (int mi = 0; mi < 2; mi++)
                #pragma unroll
                for (int nj = 0; nj < 8; nj++) {
                    asm volatile(
                        "mma.sync.aligned.m16n8k8.row.col.f32.tf32.tf32.f32 "
                        "{%0,%1,%2,%3}, {%4,%5,%6,%7}, {%8,%9}, {%0,%1,%2,%3};"
                        : "+f"(acc[mi][nj][0]), "+f"(acc[mi][nj][1]),
                          "+f"(acc[mi][nj][2]), "+f"(acc[mi][nj][3])
                        : "r"(af[mi][0]), "r"(af[mi][1]), "r"(af[mi][2]), "r"(af[mi][3]),
                          "r"(bf[nj][0]), "r"(bf[nj][1]));
                }
        }
        __syncthreads();
    }

    #pragma unroll
    for (int mi = 0; mi < 2; mi++) {
        int r_lo = row0 + mrow + mi * 16 + g;
        int r_hi = r_lo + 8;
        #pragma unroll
        for (int nj = 0; nj < 8; nj++) {
            int col = ncol + nj * 8 + 2 * t;
            float b0 = bias[col], b1 = bias[col + 1];
            float2 v0, v1;
            v0.x = acc[mi][nj][0] + b0; v0.y = acc[mi][nj][1] + b1;
            v1.x = acc[mi][nj][2] + b0; v1.y = acc[mi][nj][3] + b1;
            if (relu) {
                v0.x = fmaxf(v0.x, 0.f); v0.y = fmaxf(v0.y, 0.f);
                v1.x = fmaxf(v1.x, 0.f); v1.y = fmaxf(v1.y, 0.f);
            }
            if (r_lo < NN) *(float2*)&C[(size_t)r_lo * 128 + col] = v0;
            if (r_hi < NN) *(float2*)&C[(size_t)r_hi * 128 + col] = v1;
        }
    }
}

// ---------------- layernorm + relu + residual-add: h += relu(LN(u)) ----------------
__global__ __launch_bounds__(256) void ln_res_kernel(const float* __restrict__ u,
                                                     const float* __restrict__ g,
                                                     const float* __restrict__ b,
                                                     float* __restrict__ h) {
    int warp = (blockIdx.x * blockDim.x + threadIdx.x) >> 5;
    int lane = threadIdx.x & 31;
    if (warp >= NN) return;
    float4 v = ((const float4*)(u + (size_t)warp * 128))[lane];
    float s = v.x + v.y + v.z + v.w;
    #pragma unroll
    for (int d = 16; d; d >>= 1) s += __shfl_xor_sync(0xffffffffu, s, d);
    float mu = s * (1.0f / 128.0f);
    float dx = v.x - mu, dy = v.y - mu, dz = v.z - mu, dw = v.w - mu;
    float q = dx * dx + dy * dy + dz * dz + dw * dw;
    #pragma unroll
    for (int d = 16; d; d >>= 1) q += __shfl_xor_sync(0xffffffffu, q, d);
    float r = rsqrtf(q * (1.0f / 128.0f) + 1e-5f);
    float4 gg = ((const float4*)g)[lane];
    float4 bb = ((const float4*)b)[lane];
    float4* hp = (float4*)(h + (size_t)warp * 128);
    float4 hv = hp[lane];
    hv.x += fmaxf(dx * r * gg.x + bb.x, 0.f);
    hv.y += fmaxf(dy * r * gg.y + bb.y, 0.f);
    hv.z += fmaxf(dz * r * gg.z + bb.z, 0.f);
    hv.w += fmaxf(dw * r * gg.w + bb.w, 0.f);
    hp[lane] = hv;
}

// ---------------- layer 4: project h to scalars ----------------
__global__ __launch_bounds__(256) void gemv4_kernel(const float* __restrict__ h,
                                                    const float* __restrict__ wl,
                                                    const float* __restrict__ wr) {
    int warp = (blockIdx.x * blockDim.x + threadIdx.x) >> 5;
    int lane = threadIdx.x & 31;
    if (warp >= NN) return;
    float4 v = ((const float4*)(h + (size_t)warp * 128))[lane];
    float4 a = __ldg((const float4*)wl + lane);
    float4 b = __ldg((const float4*)wr + lane);
    float sl = v.x * a.x + v.y * a.y + v.z * a.z + v.w * a.w;
    float sr = v.x * b.x + v.y * b.y + v.z * b.z + v.w * b.w;
    #pragma unroll
    for (int d = 16; d; d >>= 1) {
        sl += __shfl_xor_sync(0xffffffffu, sl, d);
        sr += __shfl_xor_sync(0xffffffffu, sr, d);
    }
    if (lane == 0) { g_zl[warp] = sl; g_zr[warp] = sr; }
}

__global__ void final_kernel(const float* __restrict__ b4, float* __restrict__ out) {
    int i = blockIdx.x * blockDim.x + threadIdx.x;
    if (i >= NN) return;
    int s = g_rowptr[i], e = g_rowptr[i + 1];
    float sum = 0.f;
    int j = s;
    for (; j + 4 <= e; j += 4) {
        float z0 = __ldg(&g_zl[g_csr[j]]);
        float z1 = __ldg(&g_zl[g_csr[j + 1]]);
        float z2 = __ldg(&g_zl[g_csr[j + 2]]);
        float z3 = __ldg(&g_zl[g_csr[j + 3]]);
        sum += (z0 + z1) + (z2 + z3);
    }
    for (; j < e; j++) sum += __ldg(&g_zl[g_csr[j]]);
    out[i] = g_zr[i] + b4[0] + g_deginv[i] * sum;
}

// ---------------- host ----------------
template <typename T>
static T* sym(const void* s) {
    void* p = nullptr;
    cudaGetSymbolAddress(&p, s);
    return (T*)p;
}

extern "C" void kernel_launch(void* const* d_in, const int* in_sizes, int n_in,
                              void* d_out, int out_size) {
    const float* x    = (const float*)d_in[0];
    const int*   ei   = (const int*)d_in[1];     // int32 (JAX x64 disabled)
    const float* Wl1  = (const float*)d_in[2];
    const float* Wr1  = (const float*)d_in[3];
    const float* b1   = (const float*)d_in[4];
    const float* ln_g = (const float*)d_in[5];
    const float* ln_b = (const float*)d_in[6];
    const float* Wres = (const float*)d_in[7];
    const float* bres = (const float*)d_in[8];
    const float* Wl2  = (const float*)d_in[9];
    const float* Wr2  = (const float*)d_in[10];
    const float* b2   = (const float*)d_in[11];
    const float* Wl3  = (const float*)d_in[12];
    const float* Wr3  = (const float*)d_in[13];
    const float* b3   = (const float*)d_in[14];
    const float* Wl4  = (const float*)d_in[15];
    const float* Wr4  = (const float*)d_in[16];
    const float* b4   = (const float*)d_in[17];
    float* out = (float*)d_out;

    float* hp   = sym<float>(g_h);
    float* tmpp = sym<float>(g_tmp);
    float* aggp = sym<float>(g_agg);

    const int warpBlocks = (NN + 7) / 8;
    const int gemmBlocks = (NN + 127) / 128;      // 782
    const int edgeBlocks = (EE + 255) / 256;
    const int nodeBlocks = (NN + 255) / 256;

    // CSR build (parallel 3-pass scan)
    k_init<<<nodeBlocks, 256>>>();
    k_count<<<edgeBlocks, 256>>>(ei);
    k_scan1<<<NB, 1024>>>();
    k_scan2<<<1, 128>>>();
    k_scan3<<<NB, 1024>>>();
    k_fill<<<edgeBlocks, 256>>>(ei);

    // Layer 1
    agg_kernel<64><<<warpBlocks, 256>>>(x, aggp);
    // residual: h = x @ Wres + bres
    gemm_tc<<<gemmBlocks, 256>>>(x, Wres, nullptr, nullptr, bres, hp, 64, 0, 0);
    // u = agg @ Wl1 + x @ Wr1 + b1
    gemm_tc<<<gemmBlocks, 256>>>(aggp, Wl1, x, Wr1, b1, tmpp, 64, 1, 0);
    // h += relu(LN(u))
    ln_res_kernel<<<warpBlocks, 256>>>(tmpp, ln_g, ln_b, hp);

    // Layer 2: tmp = relu(agg(h) @ Wl2 + h @ Wr2 + b2)
    agg_kernel<128><<<warpBlocks, 256>>>(hp, aggp);
    gemm_tc<<<gemmBlocks, 256>>>(aggp, Wl2, hp, Wr2, b2, tmpp, 128, 1, 1);

    // Layer 3: h = relu(agg(tmp) @ Wl3 + tmp @ Wr3 + b3)
    agg_kernel<128><<<warpBlocks, 256>>>(tmpp, aggp);
    gemm_tc<<<gemmBlocks, 256>>>(aggp, Wl3, tmpp, Wr3, b3, hp, 128, 1, 1);

    // Layer 4
    gemv4_kernel<<<warpBlocks, 256>>>(hp, Wl4, Wr4);
    final_kernel<<<nodeBlocks, 256>>>(b4, out);
}

// round 7
// speedup vs baseline: 1.1568x; 1.0207x over previous
#include <cuda_runtime.h>
#include <cstdint>

#define NN 100000
#define EE 1600000
#define HH 128
#define NB ((NN + 1023) / 1024)   // 98 scan tiles

// ---------------- scratch (device globals; allocation-free) ----------------
__device__ float g_h[(size_t)NN * HH];
__device__ float g_tmp[(size_t)NN * HH];
__device__ float g_agg[(size_t)NN * HH];
__device__ float g_deginv[NN];
__device__ int   g_deg[NN];
__device__ int   g_cursor[NN];
__device__ int   g_rowptr[NN + 1];
__device__ int   g_bsum[NB];
__device__ int   g_csr[EE];
__device__ float g_zl[NN];
__device__ float g_zr[NN];

// ---------------- CSR build ----------------
__global__ void k_init() {
    int i = blockIdx.x * blockDim.x + threadIdx.x;
    if (i < NN) { g_deg[i] = 0; g_cursor[i] = 0; }
}

// edge_index is int32 (JAX x64 disabled => jnp.int64 silently becomes int32)
__global__ void k_count(const int* __restrict__ ei) {
    int e = blockIdx.x * blockDim.x + threadIdx.x;
    if (e >= EE) return;
    int d = ei[EE + e];
    d = min(max(d, 0), NN - 1);
    atomicAdd(&g_deg[d], 1);
}

// pass 1: per-tile (1024) exclusive scan; tile totals to g_bsum; deginv
__global__ __launch_bounds__(1024) void k_scan1() {
    __shared__ int wsum[32];
    int t = threadIdx.x;
    int lane = t & 31, w = t >> 5;
    int i = blockIdx.x * 1024 + t;
    int v = (i < NN) ? g_deg[i] : 0;
    int x = v;
    #pragma unroll
    for (int d = 1; d < 32; d <<= 1) {
        int y = __shfl_up_sync(0xffffffffu, x, d);
        if (lane >= d) x += y;
    }
    if (lane == 31) wsum[w] = x;
    __syncthreads();
    if (w == 0) {
        int s = wsum[lane];
        #pragma unroll
        for (int d = 1; d < 32; d <<= 1) {
            int y = __shfl_up_sync(0xffffffffu, s, d);
            if (lane >= d) s += y;
        }
        wsum[lane] = s;
    }
    __syncthreads();
    int incl = x + (w > 0 ? wsum[w - 1] : 0);
    if (i < NN) {
        g_rowptr[i] = incl - v;                       // tile-local exclusive
        g_deginv[i] = 1.0f / fmaxf((float)v, 1.0f);
    }
    if (t == 1023) g_bsum[blockIdx.x] = incl;         // tile total
}

// pass 2 (merged): each block adds sum of preceding tile totals
__global__ __launch_bounds__(1024) void k_scan3() {
    __shared__ int ssum[32];
    int t = threadIdx.x;
    int lane = t & 31, w = t >> 5;
    // reduce g_bsum[0 .. blockIdx.x)
    int v = (t < blockIdx.x) ? g_bsum[t] : 0;         // blockIdx.x <= 97 < 1024
    #pragma unroll
    for (int d = 16; d; d >>= 1) v += __shfl_xor_sync(0xffffffffu, v, d);
    if (lane == 0) ssum[w] = v;
    __syncthreads();
    if (w == 0) {
        int s = (lane < 32) ? ssum[lane] : 0;
        #pragma unroll
        for (int d = 16; d; d >>= 1) s += __shfl_xor_sync(0xffffffffu, s, d);
        if (lane == 0) ssum[0] = s;
    }
    __syncthreads();
    int off = ssum[0];
    int i = blockIdx.x * 1024 + t;
    if (i < NN) g_rowptr[i] += off;
    if (blockIdx.x == 0 && t == 0) g_rowptr[NN] = EE; // every edge clamped in-range
}

__global__ void k_fill(const int* __restrict__ ei) {
    int e = blockIdx.x * blockDim.x + threadIdx.x;
    if (e >= EE) return;
    int s = ei[e];
    int d = ei[EE + e];
    s = min(max(s, 0), NN - 1);
    d = min(max(d, 0), NN - 1);
    int p = atomicAdd(&g_cursor[d], 1);
    g_csr[g_rowptr[d] + p] = s;
}

// ---------------- aggregation: warp per dst node, fp32 gather, 8-way MLP ----------------
template <int F>
__global__ __launch_bounds__(256) void agg_kernel(const float* __restrict__ in,
                                                  float* __restrict__ out) {
    int warp = (blockIdx.x * blockDim.x + threadIdx.x) >> 5;
    int lane = threadIdx.x & 31;
    if (warp >= NN) return;
    int s = g_rowptr[warp], e = g_rowptr[warp + 1];
    float dinv = g_deginv[warp];
    if (F == 128) {
        float a0 = 0.f, a1 = 0.f, a2 = 0.f, a3 = 0.f;
        int j = s;
        for (; j + 8 <= e; j += 8) {
            int i0 = g_csr[j],     i1 = g_csr[j + 1], i2 = g_csr[j + 2], i3 = g_csr[j + 3];
            int i4 = g_csr[j + 4], i5 = g_csr[j + 5], i6 = g_csr[j + 6], i7 = g_csr[j + 7];
            float4 v0 = __ldg((const float4*)(in + (size_t)i0 * 128) + lane);
            float4 v1 = __ldg((const float4*)(in + (size_t)i1 * 128) + lane);
            float4 v2 = __ldg((const float4*)(in + (size_t)i2 * 128) + lane);
            float4 v3 = __ldg((const float4*)(in + (size_t)i3 * 128) + lane);
            float4 v4 = __ldg((const float4*)(in + (size_t)i4 * 128) + lane);
            float4 v5 = __ldg((const float4*)(in + (size_t)i5 * 128) + lane);
            float4 v6 = __ldg((const float4*)(in + (size_t)i6 * 128) + lane);
            float4 v7 = __ldg((const float4*)(in + (size_t)i7 * 128) + lane);
            a0 += ((v0.x + v1.x) + (v2.x + v3.x)) + ((v4.x + v5.x) + (v6.x + v7.x));
            a1 += ((v0.y + v1.y) + (v2.y + v3.y)) + ((v4.y + v5.y) + (v6.y + v7.y));
            a2 += ((v0.z + v1.z) + (v2.z + v3.z)) + ((v4.z + v5.z) + (v6.z + v7.z));
            a3 += ((v0.w + v1.w) + (v2.w + v3.w)) + ((v4.w + v5.w) + (v6.w + v7.w));
        }
        for (; j + 4 <= e; j += 4) {
            int i0 = g_csr[j], i1 = g_csr[j + 1], i2 = g_csr[j + 2], i3 = g_csr[j + 3];
            float4 v0 = __ldg((const float4*)(in + (size_t)i0 * 128) + lane);
            float4 v1 = __ldg((const float4*)(in + (size_t)i1 * 128) + lane);
            float4 v2 = __ldg((const float4*)(in + (size_t)i2 * 128) + lane);
            float4 v3 = __ldg((const float4*)(in + (size_t)i3 * 128) + lane);
            a0 += (v0.x + v1.x) + (v2.x + v3.x);
            a1 += (v0.y + v1.y) + (v2.y + v3.y);
            a2 += (v0.z + v1.z) + (v2.z + v3.z);
            a3 += (v0.w + v1.w) + (v2.w + v3.w);
        }
        for (; j < e; j++) {
            int src = g_csr[j];
            float4 v = __ldg((const float4*)(in + (size_t)src * 128) + lane);
            a0 += v.x; a1 += v.y; a2 += v.z; a3 += v.w;
        }
        float4 o; o.x = a0 * dinv; o.y = a1 * dinv; o.z = a2 * dinv; o.w = a3 * dinv;
        ((float4*)(out + (size_t)warp * 128))[lane] = o;
    } else {  // F == 64
        float a0 = 0.f, a1 = 0.f;
        int j = s;
        for (; j + 8 <= e; j += 8) {
            int i0 = g_csr[j],     i1 = g_csr[j + 1], i2 = g_csr[j + 2], i3 = g_csr[j + 3];
            int i4 = g_csr[j + 4], i5 = g_csr[j + 5], i6 = g_csr[j + 6], i7 = g_csr[j + 7];
            float2 v0 = __ldg((const float2*)(in + (size_t)i0 * 64) + lane);
            float2 v1 = __ldg((const float2*)(in + (size_t)i1 * 64) + lane);
            float2 v2 = __ldg((const float2*)(in + (size_t)i2 * 64) + lane);
            float2 v3 = __ldg((const float2*)(in + (size_t)i3 * 64) + lane);
            float2 v4 = __ldg((const float2*)(in + (size_t)i4 * 64) + lane);
            float2 v5 = __ldg((const float2*)(in + (size_t)i5 * 64) + lane);
            float2 v6 = __ldg((const float2*)(in + (size_t)i6 * 64) + lane);
            float2 v7 = __ldg((const float2*)(in + (size_t)i7 * 64) + lane);
            a0 += ((v0.x + v1.x) + (v2.x + v3.x)) + ((v4.x + v5.x) + (v6.x + v7.x));
            a1 += ((v0.y + v1.y) + (v2.y + v3.y)) + ((v4.y + v5.y) + (v6.y + v7.y));
        }
        for (; j + 4 <= e; j += 4) {
            int i0 = g_csr[j], i1 = g_csr[j + 1], i2 = g_csr[j + 2], i3 = g_csr[j + 3];
            float2 v0 = __ldg((const float2*)(in + (size_t)i0 * 64) + lane);
            float2 v1 = __ldg((const float2*)(in + (size_t)i1 * 64) + lane);
            float2 v2 = __ldg((const float2*)(in + (size_t)i2 * 64) + lane);
            float2 v3 = __ldg((const float2*)(in + (size_t)i3 * 64) + lane);
            a0 += (v0.x + v1.x) + (v2.x + v3.x);
            a1 += (v0.y + v1.y) + (v2.y + v3.y);
        }
        for (; j < e; j++) {
            int src = g_csr[j];
            float2 v = __ldg((const float2*)(in + (size_t)src * 64) + lane);
            a0 += v.x; a1 += v.y;
        }
        float2 o; o.x = a0 * dinv; o.y = a1 * dinv;
        ((float2*)(out + (size_t)warp * 64))[lane] = o;
    }
}

// ---------------- tf32 mma.sync GEMM ----------------
__device__ __forceinline__ uint32_t f2tf32(float x) {
    uint32_t r;
    asm("cvt.rna.tf32.f32 %0, %1;" : "=r"(r) : "f"(x));
    return r;
}

#define SA_STRIDE 36
#define SB_STRIDE 132

__global__ __launch_bounds__(256, 2) void gemm_tc(
    const float* __restrict__ A1, const float* __restrict__ W1,
    const float* __restrict__ A2, const float* __restrict__ W2,
    const float* __restrict__ bias, float* __restrict__ C,
    int K, int dual, int relu)
{
    __shared__ uint32_t sA[128 * SA_STRIDE];
    __shared__ uint32_t sB[32 * SB_STRIDE];

    int tid = threadIdx.x;
    int wid = tid >> 5, lane = tid & 31;
    int g = lane >> 2, t = lane & 3;
    int row0 = blockIdx.x * 128;
    int mrow = (wid & 3) * 32;
    int ncol = (wid >> 2) * 64;

    float acc[2][8][4];
    #pragma unroll
    for (int mi = 0; mi < 2; mi++)
        #pragma unroll
        for (int nj = 0; nj < 8; nj++)
            #pragma unroll
            for (int q = 0; q < 4; q++) acc[mi][nj][q] = 0.f;

    int KT = dual ? 2 * K : K;
    for (int k0 = 0; k0 < KT; k0 += 32) {
        const float* A = A1;
        const float* W = W1;
        int kk = k0;
        if (k0 >= K) { A = A2; W = W2; kk = k0 - K; }

        #pragma unroll
        for (int it = 0; it < 4; it++) {
            int idx = tid + it * 256;
            int r = idx >> 3;
            int c4 = idx & 7;
            float4 v = make_float4(0.f, 0.f, 0.f, 0.f);
            int gr = row0 + r;
            if (gr < NN) v = *(const float4*)&A[(size_t)gr * K + kk + c4 * 4];
            uint32_t* p = &sA[r * SA_STRIDE + c4 * 4];
            p[0] = f2tf32(v.x); p[1] = f2tf32(v.y);
            p[2] = f2tf32(v.z); p[3] = f2tf32(v.w);
        }
        #pragma unroll
        for (int it = 0; it < 4; it++) {
            int idx = tid + it * 256;
            int kr = idx >> 5;
            int n4 = idx & 31;
            float4 v = *(const float4*)&W[(size_t)(kk + kr) * 128 + n4 * 4];
            uint32_t* p = &sB[kr * SB_STRIDE + n4 * 4];
            p[0] = f2tf32(v.x); p[1] = f2tf32(v.y);
            p[2] = f2tf32(v.z); p[3] = f2tf32(v.w);
        }
        __syncthreads();

        #pragma unroll
        for (int ks = 0; ks < 4; ks++) {
            int k = ks * 8;
            uint32_t af[2][4];
            #pragma unroll
            for (int mi = 0; mi < 2; mi++) {
                int br = mrow + mi * 16;
                af[mi][0] = sA[(br + g) * SA_STRIDE + k + t];
                af[mi][1] = sA[(br + g + 8) * SA_STRIDE + k + t];
                af[mi][2] = sA[(br + g) * SA_STRIDE + k + t + 4];
                af[mi][3] = sA[(br + g + 8) * SA_STRIDE + k + t + 4];
            }
            uint32_t bf[8][2];
            #pragma unroll
            for (int nj = 0; nj < 8; nj++) {
                int col = ncol + nj * 8 + g;
                bf[nj][0] = sB[(k + t) * SB_STRIDE + col];
                bf[nj][1] = sB[(k + t + 4) * SB_STRIDE + col];
            }
            #pragma unroll
            for (int mi = 0; mi < 2; mi++)
                #pragma unroll
                for (int nj = 0; nj < 8; nj++) {
                    asm volatile(
                        "mma.sync.aligned.m16n8k8.row.col.f32.tf32.tf32.f32 "
                        "{%0,%1,%2,%3}, {%4,%5,%6,%7}, {%8,%9}, {%0,%1,%2,%3};"
                        : "+f"(acc[mi][nj][0]), "+f"(acc[mi][nj][1]),
                          "+f"(acc[mi][nj][2]), "+f"(acc[mi][nj][3])
                        : "r"(af[mi][0]), "r"(af[mi][1]), "r"(af[mi][2]), "r"(af[mi][3]),
                          "r"(bf[nj][0]), "r"(bf[nj][1]));
                }
        }
        __syncthreads();
    }

    #pragma unroll
    for (int mi = 0; mi < 2; mi++) {
        int r_lo = row0 + mrow + mi * 16 + g;
        int r_hi = r_lo + 8;
        #pragma unroll
        for (int nj = 0; nj < 8; nj++) {
            int col = ncol + nj * 8 + 2 * t;
            float b0 = bias[col], b1 = bias[col + 1];
            float2 v0, v1;
            v0.x = acc[mi][nj][0] + b0; v0.y = acc[mi][nj][1] + b1;
            v1.x = acc[mi][nj][2] + b0; v1.y = acc[mi][nj][3] + b1;
            if (relu) {
                v0.x = fmaxf(v0.x, 0.f); v0.y = fmaxf(v0.y, 0.f);
                v1.x = fmaxf(v1.x, 0.f); v1.y = fmaxf(v1.y, 0.f);
            }
            if (r_lo < NN) *(float2*)&C[(size_t)r_lo * 128 + col] = v0;
            if (r_hi < NN) *(float2*)&C[(size_t)r_hi * 128 + col] = v1;
        }
    }
}

// ---------------- layernorm + relu + residual-add: h += relu(LN(u)) ----------------
__global__ __launch_bounds__(256) void ln_res_kernel(const float* __restrict__ u,
                                                     const float* __restrict__ g,
                                                     const float* __restrict__ b,
                                                     float* __restrict__ h) {
    int warp = (blockIdx.x * blockDim.x + threadIdx.x) >> 5;
    int lane = threadIdx.x & 31;
    if (warp >= NN) return;
    float4 v = ((const float4*)(u + (size_t)warp * 128))[lane];
    float s = v.x + v.y + v.z + v.w;
    #pragma unroll
    for (int d = 16; d; d >>= 1) s += __shfl_xor_sync(0xffffffffu, s, d);
    float mu = s * (1.0f / 128.0f);
    float dx = v.x - mu, dy = v.y - mu, dz = v.z - mu, dw = v.w - mu;
    float q = dx * dx + dy * dy + dz * dz + dw * dw;
    #pragma unroll
    for (int d = 16; d; d >>= 1) q += __shfl_xor_sync(0xffffffffu, q, d);
    float r = rsqrtf(q * (1.0f / 128.0f) + 1e-5f);
    float4 gg = ((const float4*)g)[lane];
    float4 bb = ((const float4*)b)[lane];
    float4* hp = (float4*)(h + (size_t)warp * 128);
    float4 hv = hp[lane];
    hv.x += fmaxf(dx * r * gg.x + bb.x, 0.f);
    hv.y += fmaxf(dy * r * gg.y + bb.y, 0.f);
    hv.z += fmaxf(dz * r * gg.z + bb.z, 0.f);
    hv.w += fmaxf(dw * r * gg.w + bb.w, 0.f);
    hp[lane] = hv;
}

// ---------------- layer 4: project h to scalars ----------------
__global__ __launch_bounds__(256) void gemv4_kernel(const float* __restrict__ h,
                                                    const float* __restrict__ wl,
                                                    const float* __restrict__ wr) {
    int warp = (blockIdx.x * blockDim.x + threadIdx.x) >> 5;
    int lane = threadIdx.x & 31;
    if (warp >= NN) return;
    float4 v = ((const float4*)(h + (size_t)warp * 128))[lane];
    float4 a = __ldg((const float4*)wl + lane);
    float4 b = __ldg((const float4*)wr + lane);
    float sl = v.x * a.x + v.y * a.y + v.z * a.z + v.w * a.w;
    float sr = v.x * b.x + v.y * b.y + v.z * b.z + v.w * b.w;
    #pragma unroll
    for (int d = 16; d; d >>= 1) {
        sl += __shfl_xor_sync(0xffffffffu, sl, d);
        sr += __shfl_xor_sync(0xffffffffu, sr, d);
    }
    if (lane == 0) { g_zl[warp] = sl; g_zr[warp] = sr; }
}

__global__ void final_kernel(const float* __restrict__ b4, float* __restrict__ out) {
    int i = blockIdx.x * blockDim.x + threadIdx.x;
    if (i >= NN) return;
    int s = g_rowptr[i], e = g_rowptr[i + 1];
    float sum = 0.f;
    int j = s;
    for (; j + 4 <= e; j += 4) {
        float z0 = __ldg(&g_zl[g_csr[j]]);
        float z1 = __ldg(&g_zl[g_csr[j + 1]]);
        float z2 = __ldg(&g_zl[g_csr[j + 2]]);
        float z3 = __ldg(&g_zl[g_csr[j + 3]]);
        sum += (z0 + z1) + (z2 + z3);
    }
    for (; j < e; j++) sum += __ldg(&g_zl[g_csr[j]]);
    out[i] = g_zr[i] + b4[0] + g_deginv[i] * sum;
}

// ---------------- host ----------------
template <typename T>
static T* sym(const void* s) {
    void* p = nullptr;
    cudaGetSymbolAddress(&p, s);
    return (T*)p;
}

extern "C" void kernel_launch(void* const* d_in, const int* in_sizes, int n_in,
                              void* d_out, int out_size) {
    const float* x    = (const float*)d_in[0];
    const int*   ei   = (const int*)d_in[1];     // int32 (JAX x64 disabled)
    const float* Wl1  = (const float*)d_in[2];
    const float* Wr1  = (const float*)d_in[3];
    const float* b1   = (const float*)d_in[4];
    const float* ln_g = (const float*)d_in[5];
    const float* ln_b = (const float*)d_in[6];
    const float* Wres = (const float*)d_in[7];
    const float* bres = (const float*)d_in[8];
    const float* Wl2  = (const float*)d_in[9];
    const float* Wr2  = (const float*)d_in[10];
    const float* b2   = (const float*)d_in[11];
    const float* Wl3  = (const float*)d_in[12];
    const float* Wr3  = (const float*)d_in[13];
    const float* b3   = (const float*)d_in[14];
    const float* Wl4  = (const float*)d_in[15];
    const float* Wr4  = (const float*)d_in[16];
    const float* b4   = (const float*)d_in[17];
    float* out = (float*)d_out;

    float* hp   = sym<float>(g_h);
    float* tmpp = sym<float>(g_tmp);
    float* aggp = sym<float>(g_agg);

    const int warpBlocks = (NN + 7) / 8;
    const int gemmBlocks = (NN + 127) / 128;      // 782
    const int edgeBlocks = (EE + 255) / 256;
    const int nodeBlocks = (NN + 255) / 256;

    // CSR build (2-pass scan; scan2 merged into scan3)
    k_init<<<nodeBlocks, 256>>>();
    k_count<<<edgeBlocks, 256>>>(ei);
    k_scan1<<<NB, 1024>>>();
    k_scan3<<<NB, 1024>>>();
    k_fill<<<edgeBlocks, 256>>>(ei);

    // Layer 1
    agg_kernel<64><<<warpBlocks, 256>>>(x, aggp);
    // residual: h = x @ Wres + bres
    gemm_tc<<<gemmBlocks, 256>>>(x, Wres, nullptr, nullptr, bres, hp, 64, 0, 0);
    // u = agg @ Wl1 + x @ Wr1 + b1
    gemm_tc<<<gemmBlocks, 256>>>(aggp, Wl1, x, Wr1, b1, tmpp, 64, 1, 0);
    // h += relu(LN(u))
    ln_res_kernel<<<warpBlocks, 256>>>(tmpp, ln_g, ln_b, hp);

    // Layer 2: tmp = relu(agg(h) @ Wl2 + h @ Wr2 + b2)
    agg_kernel<128><<<warpBlocks, 256>>>(hp, aggp);
    gemm_tc<<<gemmBlocks, 256>>>(aggp, Wl2, hp, Wr2, b2, tmpp, 128, 1, 1);

    // Layer 3: h = relu(agg(tmp) @ Wl3 + tmp @ Wr3 + b3)
    agg_kernel<128><<<warpBlocks, 256>>>(tmpp, aggp);
    gemm_tc<<<gemmBlocks, 256>>>(aggp, Wl3, tmpp, Wr3, b3, hp, 128, 1, 1);

    // Layer 4
    gemv4_kernel<<<warpBlocks, 256>>>(hp, Wl4, Wr4);
    final_kernel<<<nodeBlocks, 256>>>(b4, out);
}